// round 11
// baseline (speedup 1.0000x reference)
#include <cuda_runtime.h>
#include <cuda_bf16.h>
#include <cuda_fp16.h>
#include <math.h>
#include <string.h>

// ContrastiveLoss: N=8192 points, D=64, labels int32 in [0,8).
// loss = [ sum_{same-label,i!=j} d2  +  sum_{diff-label} max(1-d,0)^2 ] / (N*(N-1))
//
//   pos term: exact closed form per class: sum d2 = 2*(n_c*S2_c - |S1_c|^2)  (O(N*D))
//   neg term: nonzero only when d < 1. fp16 pair-packed 8-dim partial distance with
//             a generous threshold (d2_8 < 2.0, worst-case fp16 error < 0.35) is a
//             guaranteed screen -> survivors compacted to smem, exactly re-evaluated
//             in fp32/fp64 on all 64 dims. Overflow -> exact fp32 tile re-screen.
// Accumulators are zero at module load and re-zeroed by finalize after each use.

#define N_PTS 8192
#define NDIM  64
#define NCLS  8
#define TI    512     // i-rows per screen block (4 per thread)
#define TJ    128     // j-rows per screen block
#define SCAP  2048    // survivor buffer entries per block

__device__ float  g_s1[NCLS * NDIM];   // per-class vector sums (RED.ADD targets)
__device__ float  g_s2[NCLS * NDIM];   // per-class per-dim sum of squares
__device__ int    g_hist[NCLS];        // class histogram
__device__ double g_neg;

// ---------------- K1: prep (per-class sums + histogram, smem-reduced) ---------
// grid 256 x 256 threads. Block b: rows [b*32, b*32+32).
// Thread t: k = t&63 (dim), g = t>>6 (row group of 8).
__global__ void __launch_bounds__(256) prep_kernel(const float* __restrict__ X,
                                                   const int* __restrict__ lab) {
    int t  = threadIdx.x;
    int k  = t & 63;
    int g  = t >> 6;
    int r0 = blockIdx.x * 32 + g * 8;

    __shared__ int   slab[32];
    __shared__ float red1[4][NCLS * NDIM];
    __shared__ float red2[4][NCLS * NDIM];
    if (t < 32) slab[t] = lab[blockIdx.x * 32 + t];
    __syncthreads();

    float a1[NCLS], a2[NCLS];
#pragma unroll
    for (int c = 0; c < NCLS; c++) { a1[c] = 0.0f; a2[c] = 0.0f; }
#pragma unroll
    for (int rr = 0; rr < 8; ++rr) {
        float v  = X[(r0 + rr) * NDIM + k];
        float v2 = v * v;
        int   c  = slab[g * 8 + rr];
#pragma unroll
        for (int cc = 0; cc < NCLS; cc++) {
            bool m = (cc == c);
            a1[cc] += m ? v  : 0.0f;
            a2[cc] += m ? v2 : 0.0f;
        }
    }
#pragma unroll
    for (int cc = 0; cc < NCLS; cc++) {
        red1[g][cc * NDIM + k] = a1[cc];
        red2[g][cc * NDIM + k] = a2[cc];
    }
    __syncthreads();
#pragma unroll
    for (int q = 0; q < 2; q++) {
        int idx = q * 256 + t;
        float s1 = red1[0][idx] + red1[1][idx] + red1[2][idx] + red1[3][idx];
        float s2 = red2[0][idx] + red2[1][idx] + red2[2][idx] + red2[3][idx];
        atomicAdd(&g_s1[idx], s1);
        atomicAdd(&g_s2[idx], s2);
    }
    if (t < NCLS) {
        int cnt = 0;
#pragma unroll
        for (int rr = 0; rr < 32; rr++) cnt += (slab[rr] == t) ? 1 : 0;
        atomicAdd(&g_hist[t], cnt);
    }
}

// ---------------- rare path: exact 64-dim evaluation ----------------
__device__ __noinline__ void eval_pair(const float* __restrict__ X,
                                       const int* __restrict__ lab, int i, int j) {
    if (j <= i) return;
    if (lab[i] == lab[j]) return;       // same-label handled in closed form
    const float4* xi = (const float4*)(X + i * NDIM);
    const float4* xj = (const float4*)(X + j * NDIM);
    float s = 0.0f;
#pragma unroll
    for (int q = 0; q < 16; q++) {
        float4 a = xi[q], b = xj[q];
        float d;
        d = a.x - b.x; s = fmaf(d, d, s);
        d = a.y - b.y; s = fmaf(d, d, s);
        d = a.z - b.z; s = fmaf(d, d, s);
        d = a.w - b.w; s = fmaf(d, d, s);
    }
    if (s < 1.0f) {
        float u = 1.0f - sqrtf(fmaxf(s, 0.0f));
        atomicAdd(&g_neg, 2.0 * (double)u * (double)u);   // unordered -> ordered pairs
    }
}

__device__ __forceinline__ float half_norm8f(float4 v0, float4 v1) {
    float s = v0.x * v0.x;
    s = fmaf(v0.y, v0.y, s);
    s = fmaf(v0.z, v0.z, s);
    s = fmaf(v0.w, v0.w, s);
    s = fmaf(v1.x, v1.x, s);
    s = fmaf(v1.y, v1.y, s);
    s = fmaf(v1.z, v1.z, s);
    s = fmaf(v1.w, v1.w, s);
    return 0.5f * s;
}

__device__ __forceinline__ float dot8f(float4 a0, float4 a1, float4 b0, float4 b1) {
    float s = a0.x * b0.x;
    s = fmaf(a0.y, b0.y, s);
    s = fmaf(a0.z, b0.z, s);
    s = fmaf(a0.w, b0.w, s);
    s = fmaf(a1.x, b1.x, s);
    s = fmaf(a1.y, b1.y, s);
    s = fmaf(a1.z, b1.z, s);
    s = fmaf(a1.w, b1.w, s);
    return s;
}

__device__ __forceinline__ __half2 u2h2(unsigned u) {
    __half2 h; memcpy(&h, &u, 4); return h;
}
__device__ __forceinline__ unsigned h2u(__half2 h) {
    unsigned u; memcpy(&u, &h, 4); return u;
}

// ---------------- K2: screen (fp16 pair-packed 8-dim lower bound) -------------
// grid (64, 16), 128 threads. Block (bj,bi): i in [bi*512,+512), j in [bj*128,+128).
// Keep blocks that can contain j > i pairs: bj >= 4*bi.
// Test (on half-rounded inputs): dot - hj - hi + 1 > 0  <=>  d2_8 < 2.0.
// fp16 worst-case error < 0.35 in d2 units; true survivors have d2_8 < 1.03 here,
// so none are missed. Survivors -> smem buffer -> exact fp32/fp64 evaluation.
// Per-lane verdicts via __hgt2 (half2 mask 1.0/0.0 -> bits 0x3C00 per lane).
__global__ void __launch_bounds__(128) screen_kernel(const float* __restrict__ X,
                                                     const int* __restrict__ lab) {
    int bi = blockIdx.y, bj = blockIdx.x;
    if (bj < 4 * bi) return;
    int t = threadIdx.x;

    __shared__ __align__(16) __half2 sh2[TJ / 2][8];  // [jpair][dim] -> (b_{2jp,d}, b_{2jp+1,d})
    __shared__ __half2   smh[TJ / 2];                 // (-h_{2jp}, -h_{2jp+1})
    __shared__ unsigned  sbuf[SCAP];
    __shared__ int       scnt;
    const float4* Xv = (const float4*)X;

    if (t == 0) scnt = 0;
    {
        int jr = bj * TJ + t;
        float4 f0 = Xv[jr * 16 + 0];
        float4 f1 = Xv[jr * 16 + 1];
        float fv0 = f0.x, fv1 = f0.y, fv2 = f0.z, fv3 = f0.w;
        float fv4 = f1.x, fv5 = f1.y, fv6 = f1.z, fv7 = f1.w;
        __half*  hp   = (__half*)&sh2[t >> 1][0];
        int      lane = t & 1;
        float hn = 0.0f;
        __half hd;
        float  hf;
#define CONV_STORE(d, val)                               \
        hd = __float2half_rn(val);                       \
        hf = __half2float(hd);                           \
        hn = fmaf(hf, hf, hn);                           \
        hp[2 * (d) + lane] = hd;
        CONV_STORE(0, fv0) CONV_STORE(1, fv1) CONV_STORE(2, fv2) CONV_STORE(3, fv3)
        CONV_STORE(4, fv4) CONV_STORE(5, fv5) CONV_STORE(6, fv6) CONV_STORE(7, fv7)
#undef CONV_STORE
        ((__half*)&smh[t >> 1])[lane] = __float2half_rn(-0.5f * hn);
    }

    __half2 ah[4][8], c2[4];
    int     ib[4];
#pragma unroll
    for (int r = 0; r < 4; r++) {
        ib[r] = bi * TI + r * 128 + t;
        float4 a0 = Xv[ib[r] * 16 + 0];
        float4 a1 = Xv[ib[r] * 16 + 1];
        float av[8] = {a0.x, a0.y, a0.z, a0.w, a1.x, a1.y, a1.z, a1.w};
        float hn = 0.0f;
#pragma unroll
        for (int d = 0; d < 8; d++) {
            __half hd = __float2half_rn(av[d]);
            float  hf = __half2float(hd);
            hn = fmaf(hf, hf, hn);
            ah[r][d] = __half2half2(hd);
        }
        c2[r] = __float2half2_rn(0.5f * hn - 1.0f);
    }
    __syncthreads();

    const __half2 z2 = __float2half2_rn(0.0f);
#pragma unroll 4
    for (int jp = 0; jp < TJ / 2; ++jp) {
        uint4 w0 = *(const uint4*)&sh2[jp][0];
        uint4 w1 = *(const uint4*)&sh2[jp][4];
        __half2 mh = smh[jp];
        unsigned m0, m1, m2, m3, any;
#define DOT_R(mr, r)                                                 \
        {                                                            \
            __half2 acc = __hsub2(mh, c2[r]);                        \
            acc = __hfma2(ah[r][0], u2h2(w0.x), acc);                \
            acc = __hfma2(ah[r][1], u2h2(w0.y), acc);                \
            acc = __hfma2(ah[r][2], u2h2(w0.z), acc);                \
            acc = __hfma2(ah[r][3], u2h2(w0.w), acc);                \
            acc = __hfma2(ah[r][4], u2h2(w1.x), acc);                \
            acc = __hfma2(ah[r][5], u2h2(w1.y), acc);                \
            acc = __hfma2(ah[r][6], u2h2(w1.z), acc);                \
            acc = __hfma2(ah[r][7], u2h2(w1.w), acc);                \
            mr  = h2u(__hgt2(acc, z2));                              \
        }
        DOT_R(m0, 0) DOT_R(m1, 1) DOT_R(m2, 2) DOT_R(m3, 3)
#undef DOT_R
        any = m0 | m1 | m2 | m3;
        if (any) {
            int jg0 = bj * TJ + 2 * jp;
            unsigned mm[4] = {m0, m1, m2, m3};
#pragma unroll
            for (int r = 0; r < 4; r++) {
                if (mm[r] & 0x0000FFFFu) {
                    int ix = atomicAdd(&scnt, 1);
                    if (ix < SCAP) sbuf[ix] = ((unsigned)ib[r] << 13) | (unsigned)jg0;
                }
                if (mm[r] & 0xFFFF0000u) {
                    int ix = atomicAdd(&scnt, 1);
                    if (ix < SCAP) sbuf[ix] = ((unsigned)ib[r] << 13) | (unsigned)(jg0 + 1);
                }
            }
        }
    }
    __syncthreads();

    if (scnt <= SCAP) {
        // normal path: exact evaluation of compacted survivors
        for (int q = t; q < scnt; q += 128) {
            unsigned e = sbuf[q];
            eval_pair(X, lab, (int)(e >> 13), (int)(e & 8191u));
        }
    } else {
        // overflow (rare; correctness guard): exact fp32 re-screen of this
        // thread's 4 i-rows against the whole j tile, reading from global.
#pragma unroll 1
        for (int j = 0; j < TJ; ++j) {
            int jg = bj * TJ + j;
            float4 b0 = Xv[jg * 16 + 0];
            float4 b1 = Xv[jg * 16 + 1];
            float  hj = half_norm8f(b0, b1);
#pragma unroll 1
            for (int r = 0; r < 4; r++) {
                float4 a0 = Xv[ib[r] * 16 + 0];
                float4 a1 = Xv[ib[r] * 16 + 1];
                float  hi = half_norm8f(a0, a1);
                float dot = dot8f(a0, a1, b0, b1);
                if (dot > hi + hj - 0.505f) eval_pair(X, lab, ib[r], jg);
            }
        }
    }
}

// ---------------- K3: finalize (tiny) + reset accumulators --------------------
__global__ void __launch_bounds__(512) finalize_kernel(float* __restrict__ out) {
    int t = threadIdx.x;                    // t = c*64 + k
    __shared__ double red[512];

    int c = t >> 6;
    double S1 = (double)g_s1[t];
    double S2 = (double)g_s2[t];
    red[t] = (double)g_hist[c] * S2 - S1 * S1;
    __syncthreads();
    for (int s = 256; s > 0; s >>= 1) {
        if (t < s) red[t] += red[t + s];
        __syncthreads();
    }
    if (t == 0) {
        double pos  = 2.0 * red[0];
        double loss = (pos + g_neg) / ((double)N_PTS * (double)(N_PTS - 1));
        out[0] = (float)loss;
    }
    // reset for the next graph replay (globals are 0 at module load)
    g_s1[t] = 0.0f;
    g_s2[t] = 0.0f;
    if (t < NCLS) g_hist[t] = 0;
    if (t == 0)   g_neg = 0.0;
}

extern "C" void kernel_launch(void* const* d_in, const int* in_sizes, int n_in,
                              void* d_out, int out_size) {
    const float* X   = (const float*)d_in[0];
    const int*   lab = (const int*)d_in[1];
    float*       out = (float*)d_out;

    prep_kernel<<<256, 256>>>(X, lab);
    dim3 g(64, 16);
    screen_kernel<<<g, 128>>>(X, lab);
    finalize_kernel<<<1, 512>>>(out);
}

// round 12
// speedup vs baseline: 1.2413x; 1.2413x over previous
#include <cuda_runtime.h>
#include <cuda_bf16.h>
#include <math.h>

// ContrastiveLoss: N=8192 points, D=64, labels int32 in [0,8).
// loss = [ sum_{same-label,i!=j} d2  +  sum_{diff-label} max(1-d,0)^2 ] / (N*(N-1))
//
//   pos term: exact closed form per class: sum d2 = 2*(n_c*S2_c - |S1_c|^2)  (O(N*D))
//   neg term: nonzero only when d < 1. 8-dim fp32 partial distance (dot form) is an
//             exact lower bound on d2 -> screen all pairs; survivors compacted into
//             smem (one branch region per 4 pairs, max-combined verdict), exactly
//             evaluated on all 64 dims. Compact 544-block triangular grid.
// Accumulators are zero at module load and re-zeroed by finalize after each use.

#define N_PTS 8192
#define NDIM  64
#define NCLS  8
#define TI    512     // i-rows per screen block (4 per thread)
#define TJ    128     // j-rows per screen block
#define NBI   16      // i-tiles
#define NBJ   64      // j-tiles
#define NBLK  544     // active (bi,bj) tiles: sum_{bi<16} (64-4*bi)
#define SCAP  2048    // survivor buffer entries per block

__device__ float  g_s1[NCLS * NDIM];   // per-class vector sums (RED.ADD targets)
__device__ float  g_s2[NCLS * NDIM];   // per-class per-dim sum of squares
__device__ int    g_hist[NCLS];        // class histogram
__device__ double g_neg;

// ---------------- K1: prep (per-class sums + histogram, smem-reduced) ---------
// grid 256 x 256 threads. Block b: rows [b*32, b*32+32).
__global__ void __launch_bounds__(256) prep_kernel(const float* __restrict__ X,
                                                   const int* __restrict__ lab) {
    int t  = threadIdx.x;
    int k  = t & 63;
    int g  = t >> 6;
    int r0 = blockIdx.x * 32 + g * 8;

    __shared__ int   slab[32];
    __shared__ float red1[4][NCLS * NDIM];
    __shared__ float red2[4][NCLS * NDIM];
    if (t < 32) slab[t] = lab[blockIdx.x * 32 + t];
    __syncthreads();

    float a1[NCLS], a2[NCLS];
#pragma unroll
    for (int c = 0; c < NCLS; c++) { a1[c] = 0.0f; a2[c] = 0.0f; }
#pragma unroll
    for (int rr = 0; rr < 8; ++rr) {
        float v  = X[(r0 + rr) * NDIM + k];
        float v2 = v * v;
        int   c  = slab[g * 8 + rr];
#pragma unroll
        for (int cc = 0; cc < NCLS; cc++) {
            bool m = (cc == c);
            a1[cc] += m ? v  : 0.0f;
            a2[cc] += m ? v2 : 0.0f;
        }
    }
#pragma unroll
    for (int cc = 0; cc < NCLS; cc++) {
        red1[g][cc * NDIM + k] = a1[cc];
        red2[g][cc * NDIM + k] = a2[cc];
    }
    __syncthreads();
#pragma unroll
    for (int q = 0; q < 2; q++) {
        int idx = q * 256 + t;
        float s1 = red1[0][idx] + red1[1][idx] + red1[2][idx] + red1[3][idx];
        float s2 = red2[0][idx] + red2[1][idx] + red2[2][idx] + red2[3][idx];
        atomicAdd(&g_s1[idx], s1);
        atomicAdd(&g_s2[idx], s2);
    }
    if (t < NCLS) {
        int cnt = 0;
#pragma unroll
        for (int rr = 0; rr < 32; rr++) cnt += (slab[rr] == t) ? 1 : 0;
        atomicAdd(&g_hist[t], cnt);
    }
}

// ---------------- rare path: exact 64-dim evaluation ----------------
__device__ __noinline__ void eval_pair(const float* __restrict__ X,
                                       const int* __restrict__ lab, int i, int j) {
    if (j <= i) return;                 // self pairs / j<i duplicates from diag tiles
    if (lab[i] == lab[j]) return;       // same-label handled in closed form
    const float4* xi = (const float4*)(X + i * NDIM);
    const float4* xj = (const float4*)(X + j * NDIM);
    float s = 0.0f;
#pragma unroll
    for (int q = 0; q < 16; q++) {
        float4 a = xi[q], b = xj[q];
        float d;
        d = a.x - b.x; s = fmaf(d, d, s);
        d = a.y - b.y; s = fmaf(d, d, s);
        d = a.z - b.z; s = fmaf(d, d, s);
        d = a.w - b.w; s = fmaf(d, d, s);
    }
    if (s < 1.0f) {
        float u = 1.0f - sqrtf(fmaxf(s, 0.0f));
        atomicAdd(&g_neg, 2.0 * (double)u * (double)u);   // unordered -> ordered pairs
    }
}

__device__ __forceinline__ float half_norm8(float4 v0, float4 v1) {
    float s = v0.x * v0.x;
    s = fmaf(v0.y, v0.y, s);
    s = fmaf(v0.z, v0.z, s);
    s = fmaf(v0.w, v0.w, s);
    s = fmaf(v1.x, v1.x, s);
    s = fmaf(v1.y, v1.y, s);
    s = fmaf(v1.z, v1.z, s);
    s = fmaf(v1.w, v1.w, s);
    return 0.5f * s;
}

// dot8 with baked-in constant start value
__device__ __forceinline__ float dot8c(float4 a0, float4 a1,
                                       float4 b0, float4 b1, float c0) {
    float s = fmaf(a0.x, b0.x, c0);
    s = fmaf(a0.y, b0.y, s);
    s = fmaf(a0.z, b0.z, s);
    s = fmaf(a0.w, b0.w, s);
    s = fmaf(a1.x, b1.x, s);
    s = fmaf(a1.y, b1.y, s);
    s = fmaf(a1.z, b1.z, s);
    s = fmaf(a1.w, b1.w, s);
    return s;
}

// ---------------- K2: screen (8-dim dot-form lower bound) + compaction --------
// Compact grid: 544 blocks, 128 threads. Linear id -> (bi,bj) with bj >= 4*bi.
// Block: i in [bi*512,+512) (4 rows/thread), j in [bj*128,+128).
// Pass iff dot8 - hj - hi + 0.505 > 0  <=>  8-dim partial d2 < 1.01 (exact LB).
// Verdicts for the 4 i-rows are max-combined -> one branch region per 4 pairs.
__global__ void __launch_bounds__(128) screen_kernel(const float* __restrict__ X,
                                                     const int* __restrict__ lab) {
    // decode linear block id -> (bi, bj); counts per bi: 64 - 4*bi
    int L = blockIdx.x;
    int bi = 0;
#pragma unroll
    for (int k = 0; k < NBI; k++) {
        int cnt = NBJ - 4 * k;
        bool adv = (L >= cnt);
        L  -= adv ? cnt : 0;
        bi += adv ? 1 : 0;
    }
    int bj = 4 * bi + L;
    int t  = threadIdx.x;

    __shared__ float4   sj[TJ][2];
    __shared__ float    smhj[TJ];       // -hj
    __shared__ unsigned sbuf[SCAP];
    __shared__ int      scnt;
    const float4* Xv = (const float4*)X;

    if (t == 0) scnt = 0;
    int jr = bj * TJ + t;
    float4 j0 = Xv[jr * 16 + 0];
    float4 j1 = Xv[jr * 16 + 1];
    sj[t][0] = j0;
    sj[t][1] = j1;
    smhj[t]  = -half_norm8(j0, j1);

    float4 a[4][2];
    float  ci[4];                       // hi - 0.505
    int    ib[4];
#pragma unroll
    for (int r = 0; r < 4; r++) {
        ib[r]   = bi * TI + r * 128 + t;
        a[r][0] = Xv[ib[r] * 16 + 0];
        a[r][1] = Xv[ib[r] * 16 + 1];
        ci[r]   = half_norm8(a[r][0], a[r][1]) - 0.505f;
    }
    __syncthreads();

#pragma unroll 4
    for (int j = 0; j < TJ; ++j) {
        float4 b0 = sj[j][0];
        float4 b1 = sj[j][1];
        float mhj = smhj[j];
        float d0 = dot8c(a[0][0], a[0][1], b0, b1, mhj - ci[0]);
        float d1 = dot8c(a[1][0], a[1][1], b0, b1, mhj - ci[1]);
        float d2 = dot8c(a[2][0], a[2][1], b0, b1, mhj - ci[2]);
        float d3 = dot8c(a[3][0], a[3][1], b0, b1, mhj - ci[3]);
        float mx = fmaxf(fmaxf(d0, d1), fmaxf(d2, d3));
        if (mx > 0.0f) {
            int jg = bj * TJ + j;
            float dd[4] = {d0, d1, d2, d3};
#pragma unroll
            for (int r = 0; r < 4; r++) {
                if (dd[r] > 0.0f) {
                    int ix = atomicAdd(&scnt, 1);
                    if (ix < SCAP) sbuf[ix] = ((unsigned)ib[r] << 13) | (unsigned)jg;
                }
            }
        }
    }
    __syncthreads();

    if (scnt <= SCAP) {
        // normal path: exact evaluation of compacted survivors
        for (int q = t; q < scnt; q += 128) {
            unsigned e = sbuf[q];
            eval_pair(X, lab, (int)(e >> 13), (int)(e & 8191u));
        }
    } else {
        // overflow (rare; correctness guard): direct re-screen of this tile
#pragma unroll 1
        for (int j = 0; j < TJ; ++j) {
            float4 b0 = sj[j][0];
            float4 b1 = sj[j][1];
            float mhj = smhj[j];
            int    jg = bj * TJ + j;
#pragma unroll 1
            for (int r = 0; r < 4; r++) {
                float d = dot8c(a[r][0], a[r][1], b0, b1, mhj - ci[r]);
                if (d > 0.0f) eval_pair(X, lab, ib[r], jg);
            }
        }
    }
}

// ---------------- K3: finalize (tiny) + reset accumulators --------------------
__global__ void __launch_bounds__(512) finalize_kernel(float* __restrict__ out) {
    int t = threadIdx.x;                    // t = c*64 + k
    __shared__ double red[512];

    int c = t >> 6;
    double S1 = (double)g_s1[t];
    double S2 = (double)g_s2[t];
    red[t] = (double)g_hist[c] * S2 - S1 * S1;
    __syncthreads();
    for (int s = 256; s > 0; s >>= 1) {
        if (t < s) red[t] += red[t + s];
        __syncthreads();
    }
    if (t == 0) {
        double pos  = 2.0 * red[0];
        double loss = (pos + g_neg) / ((double)N_PTS * (double)(N_PTS - 1));
        out[0] = (float)loss;
    }
    // reset for the next graph replay (globals are 0 at module load)
    g_s1[t] = 0.0f;
    g_s2[t] = 0.0f;
    if (t < NCLS) g_hist[t] = 0;
    if (t == 0)   g_neg = 0.0;
}

extern "C" void kernel_launch(void* const* d_in, const int* in_sizes, int n_in,
                              void* d_out, int out_size) {
    const float* X   = (const float*)d_in[0];
    const int*   lab = (const int*)d_in[1];
    float*       out = (float*)d_out;

    prep_kernel<<<256, 256>>>(X, lab);
    screen_kernel<<<NBLK, 128>>>(X, lab);
    finalize_kernel<<<1, 512>>>(out);
}

// round 13
// speedup vs baseline: 1.3489x; 1.0867x over previous
#include <cuda_runtime.h>
#include <cuda_bf16.h>
#include <math.h>

// ContrastiveLoss: N=8192 points, D=64, labels int32 in [0,8).
// loss = [ sum_{same-label,i!=j} d2  +  sum_{diff-label} max(1-d,0)^2 ] / (N*(N-1))
//
//   pos term: exact closed form per class: sum d2 = 2*(n_c*S2_c - |S1_c|^2)  (O(N*D))
//   neg term: nonzero only when d < 1. 8-dim fp32 partial distance (dot form) is an
//             exact lower bound on d2 -> screen all pairs; survivors compacted into
//             smem, exactly evaluated on all 64 dims. 2 i-rows/thread, 2x warps for
//             latency hiding.
// Accumulators are zero at module load and re-zeroed by finalize after each use.

#define N_PTS 8192
#define NDIM  64
#define NCLS  8
#define TI    256     // i-rows per screen block (2 per thread)
#define TJ    128     // j-rows per screen block
#define SCAP  2048    // survivor buffer entries per block

__device__ float  g_s1[NCLS * NDIM];   // per-class vector sums (RED.ADD targets)
__device__ float  g_s2[NCLS * NDIM];   // per-class per-dim sum of squares
__device__ int    g_hist[NCLS];        // class histogram
__device__ double g_neg;

// ---------------- K1: prep (per-class sums + histogram, smem-reduced) ---------
// grid 256 x 256 threads. Block b: rows [b*32, b*32+32).
__global__ void __launch_bounds__(256) prep_kernel(const float* __restrict__ X,
                                                   const int* __restrict__ lab) {
    int t  = threadIdx.x;
    int k  = t & 63;
    int g  = t >> 6;
    int r0 = blockIdx.x * 32 + g * 8;

    __shared__ int   slab[32];
    __shared__ float red1[4][NCLS * NDIM];
    __shared__ float red2[4][NCLS * NDIM];
    if (t < 32) slab[t] = lab[blockIdx.x * 32 + t];
    __syncthreads();

    float a1[NCLS], a2[NCLS];
#pragma unroll
    for (int c = 0; c < NCLS; c++) { a1[c] = 0.0f; a2[c] = 0.0f; }
#pragma unroll
    for (int rr = 0; rr < 8; ++rr) {
        float v  = X[(r0 + rr) * NDIM + k];
        float v2 = v * v;
        int   c  = slab[g * 8 + rr];
#pragma unroll
        for (int cc = 0; cc < NCLS; cc++) {
            bool m = (cc == c);
            a1[cc] += m ? v  : 0.0f;
            a2[cc] += m ? v2 : 0.0f;
        }
    }
#pragma unroll
    for (int cc = 0; cc < NCLS; cc++) {
        red1[g][cc * NDIM + k] = a1[cc];
        red2[g][cc * NDIM + k] = a2[cc];
    }
    __syncthreads();
#pragma unroll
    for (int q = 0; q < 2; q++) {
        int idx = q * 256 + t;
        float s1 = red1[0][idx] + red1[1][idx] + red1[2][idx] + red1[3][idx];
        float s2 = red2[0][idx] + red2[1][idx] + red2[2][idx] + red2[3][idx];
        atomicAdd(&g_s1[idx], s1);
        atomicAdd(&g_s2[idx], s2);
    }
    if (t < NCLS) {
        int cnt = 0;
#pragma unroll
        for (int rr = 0; rr < 32; rr++) cnt += (slab[rr] == t) ? 1 : 0;
        atomicAdd(&g_hist[t], cnt);
    }
}

// ---------------- rare path: exact 64-dim evaluation ----------------
__device__ __noinline__ void eval_pair(const float* __restrict__ X,
                                       const int* __restrict__ lab, int i, int j) {
    if (j <= i) return;                 // self pairs / duplicates from diag tiles
    if (lab[i] == lab[j]) return;       // same-label handled in closed form
    const float4* xi = (const float4*)(X + i * NDIM);
    const float4* xj = (const float4*)(X + j * NDIM);
    float s = 0.0f;
#pragma unroll
    for (int q = 0; q < 16; q++) {
        float4 a = xi[q], b = xj[q];
        float d;
        d = a.x - b.x; s = fmaf(d, d, s);
        d = a.y - b.y; s = fmaf(d, d, s);
        d = a.z - b.z; s = fmaf(d, d, s);
        d = a.w - b.w; s = fmaf(d, d, s);
    }
    if (s < 1.0f) {
        float u = 1.0f - sqrtf(fmaxf(s, 0.0f));
        atomicAdd(&g_neg, 2.0 * (double)u * (double)u);   // unordered -> ordered pairs
    }
}

__device__ __forceinline__ float half_norm8(float4 v0, float4 v1) {
    float s = v0.x * v0.x;
    s = fmaf(v0.y, v0.y, s);
    s = fmaf(v0.z, v0.z, s);
    s = fmaf(v0.w, v0.w, s);
    s = fmaf(v1.x, v1.x, s);
    s = fmaf(v1.y, v1.y, s);
    s = fmaf(v1.z, v1.z, s);
    s = fmaf(v1.w, v1.w, s);
    return 0.5f * s;
}

// ---------------- K2: screen (8-dim dot-form lower bound) + compaction --------
// grid (64, 32), 128 threads. Block (bj,bi): i in [bi*256,+256) (2 rows/thread),
// j in [bj*128,+128). Keep blocks with j>i pairs: bj >= 2*bi; fully off-diagonal
// when bj >= 2*bi+2 (skip the per-pair j>i test there).
// Pass test: dot8 - hj > hi - 0.505  <=>  partial d2 over 8 dims < 1.01 (exact LB).
__global__ void __launch_bounds__(128) screen_kernel(const float* __restrict__ X,
                                                     const int* __restrict__ lab) {
    int bi = blockIdx.y, bj = blockIdx.x;
    if (bj < 2 * bi) return;
    int t = threadIdx.x;

    __shared__ float4   sj[TJ][2];
    __shared__ float    smhj[TJ];       // -hj
    __shared__ unsigned sbuf[SCAP];
    __shared__ int      scnt;
    const float4* Xv = (const float4*)X;

    if (t == 0) scnt = 0;
    int jr = bj * TJ + t;
    float4 j0 = Xv[jr * 16 + 0];
    float4 j1 = Xv[jr * 16 + 1];
    sj[t][0] = j0;
    sj[t][1] = j1;
    smhj[t]  = -half_norm8(j0, j1);

    float4 a[2][2];
    float  ci[2];
    int    ib[2];
#pragma unroll
    for (int r = 0; r < 2; r++) {
        ib[r]   = bi * TI + r * 128 + t;
        a[r][0] = Xv[ib[r] * 16 + 0];
        a[r][1] = Xv[ib[r] * 16 + 1];
        ci[r]   = half_norm8(a[r][0], a[r][1]) - 0.505f;
    }
    __syncthreads();

    bool diag = (bj < 2 * bi + 2);
    if (!diag) {
        // fully off-diagonal: every (i,j) here has j > i
#pragma unroll 4
        for (int j = 0; j < TJ; ++j) {
            float4 b0 = sj[j][0];
            float4 b1 = sj[j][1];
            float mhj = smhj[j];
#pragma unroll
            for (int r = 0; r < 2; r++) {
                float dot = fmaf(a[r][0].x, b0.x, mhj);
                dot = fmaf(a[r][0].y, b0.y, dot);
                dot = fmaf(a[r][0].z, b0.z, dot);
                dot = fmaf(a[r][0].w, b0.w, dot);
                dot = fmaf(a[r][1].x, b1.x, dot);
                dot = fmaf(a[r][1].y, b1.y, dot);
                dot = fmaf(a[r][1].z, b1.z, dot);
                dot = fmaf(a[r][1].w, b1.w, dot);
                if (dot > ci[r]) {
                    int ix = atomicAdd(&scnt, 1);
                    if (ix < SCAP)
                        sbuf[ix] = ((unsigned)ib[r] << 13) | (unsigned)(bj * TJ + j);
                }
            }
        }
    } else {
#pragma unroll 4
        for (int j = 0; j < TJ; ++j) {
            float4 b0 = sj[j][0];
            float4 b1 = sj[j][1];
            float mhj = smhj[j];
            int    jg = bj * TJ + j;
#pragma unroll
            for (int r = 0; r < 2; r++) {
                float dot = fmaf(a[r][0].x, b0.x, mhj);
                dot = fmaf(a[r][0].y, b0.y, dot);
                dot = fmaf(a[r][0].z, b0.z, dot);
                dot = fmaf(a[r][0].w, b0.w, dot);
                dot = fmaf(a[r][1].x, b1.x, dot);
                dot = fmaf(a[r][1].y, b1.y, dot);
                dot = fmaf(a[r][1].z, b1.z, dot);
                dot = fmaf(a[r][1].w, b1.w, dot);
                if (dot > ci[r] && jg > ib[r]) {
                    int ix = atomicAdd(&scnt, 1);
                    if (ix < SCAP)
                        sbuf[ix] = ((unsigned)ib[r] << 13) | (unsigned)jg;
                }
            }
        }
    }
    __syncthreads();

    if (scnt <= SCAP) {
        // normal path: exact evaluation of compacted survivors
        for (int q = t; q < scnt; q += 128) {
            unsigned e = sbuf[q];
            eval_pair(X, lab, (int)(e >> 13), (int)(e & 8191u));
        }
    } else {
        // overflow (rare; correctness guard): direct re-screen of this tile
#pragma unroll 1
        for (int j = 0; j < TJ; ++j) {
            float4 b0 = sj[j][0];
            float4 b1 = sj[j][1];
            float mhj = smhj[j];
            int    jg = bj * TJ + j;
#pragma unroll 1
            for (int r = 0; r < 2; r++) {
                float dot = fmaf(a[r][0].x, b0.x, mhj);
                dot = fmaf(a[r][0].y, b0.y, dot);
                dot = fmaf(a[r][0].z, b0.z, dot);
                dot = fmaf(a[r][0].w, b0.w, dot);
                dot = fmaf(a[r][1].x, b1.x, dot);
                dot = fmaf(a[r][1].y, b1.y, dot);
                dot = fmaf(a[r][1].z, b1.z, dot);
                dot = fmaf(a[r][1].w, b1.w, dot);
                if (dot > ci[r]) eval_pair(X, lab, ib[r], jg);
            }
        }
    }
}

// ---------------- K3: finalize (tiny) + reset accumulators --------------------
__global__ void __launch_bounds__(512) finalize_kernel(float* __restrict__ out) {
    int t = threadIdx.x;                    // t = c*64 + k
    __shared__ double red[512];

    int c = t >> 6;
    double S1 = (double)g_s1[t];
    double S2 = (double)g_s2[t];
    red[t] = (double)g_hist[c] * S2 - S1 * S1;
    __syncthreads();
    for (int s = 256; s > 0; s >>= 1) {
        if (t < s) red[t] += red[t + s];
        __syncthreads();
    }
    if (t == 0) {
        double pos  = 2.0 * red[0];
        double loss = (pos + g_neg) / ((double)N_PTS * (double)(N_PTS - 1));
        out[0] = (float)loss;
    }
    // reset for the next graph replay (globals are 0 at module load)
    g_s1[t] = 0.0f;
    g_s2[t] = 0.0f;
    if (t < NCLS) g_hist[t] = 0;
    if (t == 0)   g_neg = 0.0;
}

extern "C" void kernel_launch(void* const* d_in, const int* in_sizes, int n_in,
                              void* d_out, int out_size) {
    const float* X   = (const float*)d_in[0];
    const int*   lab = (const int*)d_in[1];
    float*       out = (float*)d_out;

    prep_kernel<<<256, 256>>>(X, lab);
    dim3 g(64, 32);
    screen_kernel<<<g, 128>>>(X, lab);
    finalize_kernel<<<1, 512>>>(out);
}

// round 14
// speedup vs baseline: 1.6266x; 1.2059x over previous
#include <cuda_runtime.h>
#include <cuda_bf16.h>
#include <math.h>

// ContrastiveLoss: N=8192 points, D=64, labels int32 in [0,8).
// loss = [ sum_{same-label,i!=j} d2  +  sum_{diff-label} max(1-d,0)^2 ] / (N*(N-1))
//
//   pos term: exact closed form per class: sum d2 = 2*(n_c*S2_c - |S1_c|^2)  (O(N*D))
//   neg term: nonzero only when d < 1. 8-dim fp32 partial distance (dot form) is an
//             exact lower bound on d2 -> screen all pairs; survivors compacted into
//             smem, exactly evaluated on all 64 dims.
// Fused kernel: blocks [0,1056) run the screen (scheduled first), blocks
// [1056,1568) compute the pos-term partials — prep hides under the screen.
// Accumulators are zero at module load and re-zeroed by finalize after each use.

#define N_PTS 8192
#define NDIM  64
#define NCLS  8
#define TI    256     // i-rows per screen block (2 per thread)
#define TJ    128     // j-rows per screen block
#define SCAP  1024    // survivor buffer entries per block
#define NSCR  1056    // screen blocks: sum_{bi<32} (64 - 2*bi)
#define NPREP 512     // prep blocks (16 rows each)
#define NBLK  (NSCR + NPREP)

__device__ float  g_s1[NCLS * NDIM];   // per-class vector sums (RED.ADD targets)
__device__ float  g_s2[NCLS * NDIM];   // per-class per-dim sum of squares
__device__ int    g_hist[NCLS];        // class histogram
__device__ double g_neg;

// ---------------- rare path: exact 64-dim evaluation ----------------
__device__ __noinline__ void eval_pair(const float* __restrict__ X,
                                       const int* __restrict__ lab, int i, int j) {
    if (j <= i) return;                 // self pairs / duplicates from diag tiles
    if (lab[i] == lab[j]) return;       // same-label handled in closed form
    const float4* xi = (const float4*)(X + i * NDIM);
    const float4* xj = (const float4*)(X + j * NDIM);
    float s = 0.0f;
#pragma unroll
    for (int q = 0; q < 16; q++) {
        float4 a = xi[q], b = xj[q];
        float d;
        d = a.x - b.x; s = fmaf(d, d, s);
        d = a.y - b.y; s = fmaf(d, d, s);
        d = a.z - b.z; s = fmaf(d, d, s);
        d = a.w - b.w; s = fmaf(d, d, s);
    }
    if (s < 1.0f) {
        float u = 1.0f - sqrtf(fmaxf(s, 0.0f));
        atomicAdd(&g_neg, 2.0 * (double)u * (double)u);   // unordered -> ordered pairs
    }
}

__device__ __forceinline__ float half_norm8(float4 v0, float4 v1) {
    float s = v0.x * v0.x;
    s = fmaf(v0.y, v0.y, s);
    s = fmaf(v0.z, v0.z, s);
    s = fmaf(v0.w, v0.w, s);
    s = fmaf(v1.x, v1.x, s);
    s = fmaf(v1.y, v1.y, s);
    s = fmaf(v1.z, v1.z, s);
    s = fmaf(v1.w, v1.w, s);
    return 0.5f * s;
}

struct SmemScreen {
    float4   sj[TJ][2];
    float    smhj[TJ];
    unsigned sbuf[SCAP];
    int      scnt;
};
struct SmemPrep {
    int   slab[16];
    float red1[2][NCLS * NDIM];
    float red2[2][NCLS * NDIM];
};
union SmemU { SmemScreen scr; SmemPrep prep; };

// ---------------- K1: fused screen + pos-term prep ----------------------------
// 128 threads. Blocks [0,NSCR): screen tile; blocks [NSCR,NBLK): prep 16 rows.
__global__ void __launch_bounds__(128) fused_kernel(const float* __restrict__ X,
                                                    const int* __restrict__ lab) {
    __shared__ __align__(16) SmemU sm;
    int t = threadIdx.x;
    const float4* Xv = (const float4*)X;

    if (blockIdx.x >= NSCR) {
        // ---------------- prep path: rows [pb*16, pb*16+16) ----------------
        SmemPrep& sp = sm.prep;
        int pb = blockIdx.x - NSCR;
        int k  = t & 63;
        int g  = t >> 6;                      // 0 or 1: rows 0-7 / 8-15
        int r0 = pb * 16 + g * 8;
        if (t < 16) sp.slab[t] = lab[pb * 16 + t];
        __syncthreads();

        float a1[NCLS], a2[NCLS];
#pragma unroll
        for (int c = 0; c < NCLS; c++) { a1[c] = 0.0f; a2[c] = 0.0f; }
#pragma unroll
        for (int rr = 0; rr < 8; ++rr) {
            float v  = X[(r0 + rr) * NDIM + k];
            float v2 = v * v;
            int   c  = sp.slab[g * 8 + rr];
#pragma unroll
            for (int cc = 0; cc < NCLS; cc++) {
                bool m = (cc == c);
                a1[cc] += m ? v  : 0.0f;
                a2[cc] += m ? v2 : 0.0f;
            }
        }
#pragma unroll
        for (int cc = 0; cc < NCLS; cc++) {
            sp.red1[g][cc * NDIM + k] = a1[cc];
            sp.red2[g][cc * NDIM + k] = a2[cc];
        }
        __syncthreads();
        // 512 slots, 128 threads -> 4 slots each
#pragma unroll
        for (int q = 0; q < 4; q++) {
            int idx = q * 128 + t;
            atomicAdd(&g_s1[idx], sp.red1[0][idx] + sp.red1[1][idx]);
            atomicAdd(&g_s2[idx], sp.red2[0][idx] + sp.red2[1][idx]);
        }
        if (t < NCLS) {
            int cnt = 0;
#pragma unroll
            for (int rr = 0; rr < 16; rr++) cnt += (sp.slab[rr] == t) ? 1 : 0;
            atomicAdd(&g_hist[t], cnt);
        }
        return;
    }

    // ---------------- screen path ----------------
    SmemScreen& ss = sm.scr;
    // decode linear id -> (bi,bj), bj >= 2*bi, counts per bi: 64 - 2*bi
    int L = blockIdx.x;
    int bi = 0;
#pragma unroll
    for (int k = 0; k < 32; k++) {
        int cnt = 64 - 2 * k;
        bool adv = (L >= cnt);
        L  -= adv ? cnt : 0;
        bi += adv ? 1 : 0;
    }
    int bj = 2 * bi + L;

    if (t == 0) ss.scnt = 0;
    int jr = bj * TJ + t;
    float4 j0 = Xv[jr * 16 + 0];
    float4 j1 = Xv[jr * 16 + 1];
    ss.sj[t][0] = j0;
    ss.sj[t][1] = j1;
    ss.smhj[t]  = -half_norm8(j0, j1);

    float4 a[2][2];
    float  ci[2];
    int    ib[2];
#pragma unroll
    for (int r = 0; r < 2; r++) {
        ib[r]   = bi * TI + r * 128 + t;
        a[r][0] = Xv[ib[r] * 16 + 0];
        a[r][1] = Xv[ib[r] * 16 + 1];
        ci[r]   = half_norm8(a[r][0], a[r][1]) - 0.505f;
    }
    __syncthreads();

    bool diag = (bj < 2 * bi + 2);
    if (!diag) {
        // fully off-diagonal: every (i,j) here has j > i
#pragma unroll 4
        for (int j = 0; j < TJ; ++j) {
            float4 b0 = ss.sj[j][0];
            float4 b1 = ss.sj[j][1];
            float mhj = ss.smhj[j];
#pragma unroll
            for (int r = 0; r < 2; r++) {
                float dot = fmaf(a[r][0].x, b0.x, mhj);
                dot = fmaf(a[r][0].y, b0.y, dot);
                dot = fmaf(a[r][0].z, b0.z, dot);
                dot = fmaf(a[r][0].w, b0.w, dot);
                dot = fmaf(a[r][1].x, b1.x, dot);
                dot = fmaf(a[r][1].y, b1.y, dot);
                dot = fmaf(a[r][1].z, b1.z, dot);
                dot = fmaf(a[r][1].w, b1.w, dot);
                if (dot > ci[r]) {
                    int ix = atomicAdd(&ss.scnt, 1);
                    if (ix < SCAP)
                        ss.sbuf[ix] = ((unsigned)ib[r] << 13) | (unsigned)(bj * TJ + j);
                }
            }
        }
    } else {
#pragma unroll 4
        for (int j = 0; j < TJ; ++j) {
            float4 b0 = ss.sj[j][0];
            float4 b1 = ss.sj[j][1];
            float mhj = ss.smhj[j];
            int    jg = bj * TJ + j;
#pragma unroll
            for (int r = 0; r < 2; r++) {
                float dot = fmaf(a[r][0].x, b0.x, mhj);
                dot = fmaf(a[r][0].y, b0.y, dot);
                dot = fmaf(a[r][0].z, b0.z, dot);
                dot = fmaf(a[r][0].w, b0.w, dot);
                dot = fmaf(a[r][1].x, b1.x, dot);
                dot = fmaf(a[r][1].y, b1.y, dot);
                dot = fmaf(a[r][1].z, b1.z, dot);
                dot = fmaf(a[r][1].w, b1.w, dot);
                if (dot > ci[r] && jg > ib[r]) {
                    int ix = atomicAdd(&ss.scnt, 1);
                    if (ix < SCAP)
                        ss.sbuf[ix] = ((unsigned)ib[r] << 13) | (unsigned)jg;
                }
            }
        }
    }
    __syncthreads();

    if (ss.scnt <= SCAP) {
        // normal path: exact evaluation of compacted survivors
        int n = ss.scnt;
        for (int q = t; q < n; q += 128) {
            unsigned e = ss.sbuf[q];
            eval_pair(X, lab, (int)(e >> 13), (int)(e & 8191u));
        }
    } else {
        // overflow (rare; correctness guard): direct re-screen of this tile
#pragma unroll 1
        for (int j = 0; j < TJ; ++j) {
            float4 b0 = ss.sj[j][0];
            float4 b1 = ss.sj[j][1];
            float mhj = ss.smhj[j];
            int    jg = bj * TJ + j;
#pragma unroll 1
            for (int r = 0; r < 2; r++) {
                float dot = fmaf(a[r][0].x, b0.x, mhj);
                dot = fmaf(a[r][0].y, b0.y, dot);
                dot = fmaf(a[r][0].z, b0.z, dot);
                dot = fmaf(a[r][0].w, b0.w, dot);
                dot = fmaf(a[r][1].x, b1.x, dot);
                dot = fmaf(a[r][1].y, b1.y, dot);
                dot = fmaf(a[r][1].z, b1.z, dot);
                dot = fmaf(a[r][1].w, b1.w, dot);
                if (dot > ci[r]) eval_pair(X, lab, ib[r], jg);
            }
        }
    }
}

// ---------------- K2: finalize (tiny) + reset accumulators --------------------
__global__ void __launch_bounds__(512) finalize_kernel(float* __restrict__ out) {
    int t = threadIdx.x;                    // t = c*64 + k
    __shared__ double red[512];

    int c = t >> 6;
    double S1 = (double)g_s1[t];
    double S2 = (double)g_s2[t];
    red[t] = (double)g_hist[c] * S2 - S1 * S1;
    __syncthreads();
    for (int s = 256; s > 0; s >>= 1) {
        if (t < s) red[t] += red[t + s];
        __syncthreads();
    }
    if (t == 0) {
        double pos  = 2.0 * red[0];
        double loss = (pos + g_neg) / ((double)N_PTS * (double)(N_PTS - 1));
        out[0] = (float)loss;
    }
    // reset for the next graph replay (globals are 0 at module load)
    g_s1[t] = 0.0f;
    g_s2[t] = 0.0f;
    if (t < NCLS) g_hist[t] = 0;
    if (t == 0)   g_neg = 0.0;
}

extern "C" void kernel_launch(void* const* d_in, const int* in_sizes, int n_in,
                              void* d_out, int out_size) {
    const float* X   = (const float*)d_in[0];
    const int*   lab = (const int*)d_in[1];
    float*       out = (float*)d_out;

    fused_kernel<<<NBLK, 128>>>(X, lab);
    finalize_kernel<<<1, 512>>>(out);
}

// round 15
// speedup vs baseline: 1.6703x; 1.0268x over previous
#include <cuda_runtime.h>
#include <cuda_bf16.h>
#include <math.h>

// ContrastiveLoss: N=8192 points, D=64, labels int32 in [0,8).
// loss = [ sum_{same-label,i!=j} d2  +  sum_{diff-label} max(1-d,0)^2 ] / (N*(N-1))
//
//   pos term: exact closed form per class: sum d2 = 2*(n_c*S2_c - |S1_c|^2)  (O(N*D))
//   neg term: nonzero only when d < 1. 8-dim fp32 partial distance (dot form) is an
//             exact lower bound on d2 -> screen all pairs; survivors compacted into
//             smem, exactly evaluated on all 64 dims.
// ONE kernel: blocks [0,NSCR) screen, blocks [NSCR,NBLK) do pos-term prep, and the
// last block to finish (atomic ticket) reduces everything and writes the loss.
// Accumulators are zero at module load and reset by the last block each replay.

#define N_PTS 8192
#define NDIM  64
#define NCLS  8
#define TI    256     // i-rows per screen block (2 per thread)
#define TJ    128     // j-rows per screen block
#define SCAP  1024    // survivor buffer entries per block
#define NSCR  1056    // screen blocks: sum_{bi<32} (64 - 2*bi)
#define NPREP 512     // prep blocks (16 rows each)
#define NBLK  (NSCR + NPREP)

__device__ float  g_s1[NCLS * NDIM];   // per-class vector sums (RED.ADD targets)
__device__ float  g_s2[NCLS * NDIM];   // per-class per-dim sum of squares
__device__ int    g_hist[NCLS];        // class histogram
__device__ double g_neg;
__device__ int    g_done;              // completion ticket

// ---------------- rare path: exact 64-dim evaluation ----------------
__device__ __noinline__ void eval_pair(const float* __restrict__ X,
                                       const int* __restrict__ lab, int i, int j) {
    if (j <= i) return;                 // self pairs / duplicates from diag tiles
    if (lab[i] == lab[j]) return;       // same-label handled in closed form
    const float4* xi = (const float4*)(X + i * NDIM);
    const float4* xj = (const float4*)(X + j * NDIM);
    float s = 0.0f;
#pragma unroll
    for (int q = 0; q < 16; q++) {
        float4 a = xi[q], b = xj[q];
        float d;
        d = a.x - b.x; s = fmaf(d, d, s);
        d = a.y - b.y; s = fmaf(d, d, s);
        d = a.z - b.z; s = fmaf(d, d, s);
        d = a.w - b.w; s = fmaf(d, d, s);
    }
    if (s < 1.0f) {
        float u = 1.0f - sqrtf(fmaxf(s, 0.0f));
        atomicAdd(&g_neg, 2.0 * (double)u * (double)u);   // unordered -> ordered pairs
    }
}

__device__ __forceinline__ float half_norm8(float4 v0, float4 v1) {
    float s = v0.x * v0.x;
    s = fmaf(v0.y, v0.y, s);
    s = fmaf(v0.z, v0.z, s);
    s = fmaf(v0.w, v0.w, s);
    s = fmaf(v1.x, v1.x, s);
    s = fmaf(v1.y, v1.y, s);
    s = fmaf(v1.z, v1.z, s);
    s = fmaf(v1.w, v1.w, s);
    return 0.5f * s;
}

struct SmemScreen {
    float4   sj[TJ][2];
    float    smhj[TJ];
    unsigned sbuf[SCAP];
    int      scnt;
};
struct SmemPrep {
    int   slab[16];
    float red1[2][NCLS * NDIM];
    float red2[2][NCLS * NDIM];
};
union SmemU { SmemScreen scr; SmemPrep prep; };

// ---------------- the one kernel ----------------------------------------------
__global__ void __launch_bounds__(128) fused_kernel(const float* __restrict__ X,
                                                    const int* __restrict__ lab,
                                                    float* __restrict__ out) {
    __shared__ __align__(16) SmemU sm;
    __shared__ int    s_last;
    __shared__ double s_part[4];
    int t = threadIdx.x;
    const float4* Xv = (const float4*)X;

    if (blockIdx.x >= NSCR) {
        // ---------------- prep path: rows [pb*16, pb*16+16) ----------------
        SmemPrep& sp = sm.prep;
        int pb = blockIdx.x - NSCR;
        int k  = t & 63;
        int g  = t >> 6;                      // 0 or 1: rows 0-7 / 8-15
        int r0 = pb * 16 + g * 8;
        if (t < 16) sp.slab[t] = lab[pb * 16 + t];
        __syncthreads();

        float a1[NCLS], a2[NCLS];
#pragma unroll
        for (int c = 0; c < NCLS; c++) { a1[c] = 0.0f; a2[c] = 0.0f; }
#pragma unroll
        for (int rr = 0; rr < 8; ++rr) {
            float v  = X[(r0 + rr) * NDIM + k];
            float v2 = v * v;
            int   c  = sp.slab[g * 8 + rr];
#pragma unroll
            for (int cc = 0; cc < NCLS; cc++) {
                bool m = (cc == c);
                a1[cc] += m ? v  : 0.0f;
                a2[cc] += m ? v2 : 0.0f;
            }
        }
#pragma unroll
        for (int cc = 0; cc < NCLS; cc++) {
            sp.red1[g][cc * NDIM + k] = a1[cc];
            sp.red2[g][cc * NDIM + k] = a2[cc];
        }
        __syncthreads();
#pragma unroll
        for (int q = 0; q < 4; q++) {
            int idx = q * 128 + t;
            atomicAdd(&g_s1[idx], sp.red1[0][idx] + sp.red1[1][idx]);
            atomicAdd(&g_s2[idx], sp.red2[0][idx] + sp.red2[1][idx]);
        }
        if (t < NCLS) {
            int cnt = 0;
#pragma unroll
            for (int rr = 0; rr < 16; rr++) cnt += (sp.slab[rr] == t) ? 1 : 0;
            atomicAdd(&g_hist[t], cnt);
        }
    } else {
        // ---------------- screen path ----------------
        SmemScreen& ss = sm.scr;
        // decode linear id -> (bi,bj), bj >= 2*bi, counts per bi: 64 - 2*bi
        int L = blockIdx.x;
        int bi = 0;
#pragma unroll
        for (int k = 0; k < 32; k++) {
            int cnt = 64 - 2 * k;
            bool adv = (L >= cnt);
            L  -= adv ? cnt : 0;
            bi += adv ? 1 : 0;
        }
        int bj = 2 * bi + L;

        if (t == 0) ss.scnt = 0;
        int jr = bj * TJ + t;
        float4 j0 = Xv[jr * 16 + 0];
        float4 j1 = Xv[jr * 16 + 1];
        ss.sj[t][0] = j0;
        ss.sj[t][1] = j1;
        ss.smhj[t]  = -half_norm8(j0, j1);

        float4 a[2][2];
        float  ci[2];
        int    ib[2];
#pragma unroll
        for (int r = 0; r < 2; r++) {
            ib[r]   = bi * TI + r * 128 + t;
            a[r][0] = Xv[ib[r] * 16 + 0];
            a[r][1] = Xv[ib[r] * 16 + 1];
            ci[r]   = half_norm8(a[r][0], a[r][1]) - 0.505f;
        }
        __syncthreads();

        bool diag = (bj < 2 * bi + 2);
        if (!diag) {
            // fully off-diagonal: every (i,j) here has j > i
#pragma unroll 4
            for (int j = 0; j < TJ; ++j) {
                float4 b0 = ss.sj[j][0];
                float4 b1 = ss.sj[j][1];
                float mhj = ss.smhj[j];
#pragma unroll
                for (int r = 0; r < 2; r++) {
                    float dot = fmaf(a[r][0].x, b0.x, mhj);
                    dot = fmaf(a[r][0].y, b0.y, dot);
                    dot = fmaf(a[r][0].z, b0.z, dot);
                    dot = fmaf(a[r][0].w, b0.w, dot);
                    dot = fmaf(a[r][1].x, b1.x, dot);
                    dot = fmaf(a[r][1].y, b1.y, dot);
                    dot = fmaf(a[r][1].z, b1.z, dot);
                    dot = fmaf(a[r][1].w, b1.w, dot);
                    if (dot > ci[r]) {
                        int ix = atomicAdd(&ss.scnt, 1);
                        if (ix < SCAP)
                            ss.sbuf[ix] = ((unsigned)ib[r] << 13) | (unsigned)(bj * TJ + j);
                    }
                }
            }
        } else {
#pragma unroll 4
            for (int j = 0; j < TJ; ++j) {
                float4 b0 = ss.sj[j][0];
                float4 b1 = ss.sj[j][1];
                float mhj = ss.smhj[j];
                int    jg = bj * TJ + j;
#pragma unroll
                for (int r = 0; r < 2; r++) {
                    float dot = fmaf(a[r][0].x, b0.x, mhj);
                    dot = fmaf(a[r][0].y, b0.y, dot);
                    dot = fmaf(a[r][0].z, b0.z, dot);
                    dot = fmaf(a[r][0].w, b0.w, dot);
                    dot = fmaf(a[r][1].x, b1.x, dot);
                    dot = fmaf(a[r][1].y, b1.y, dot);
                    dot = fmaf(a[r][1].z, b1.z, dot);
                    dot = fmaf(a[r][1].w, b1.w, dot);
                    if (dot > ci[r] && jg > ib[r]) {
                        int ix = atomicAdd(&ss.scnt, 1);
                        if (ix < SCAP)
                            ss.sbuf[ix] = ((unsigned)ib[r] << 13) | (unsigned)jg;
                    }
                }
            }
        }
        __syncthreads();

        if (ss.scnt <= SCAP) {
            int n = ss.scnt;
            for (int q = t; q < n; q += 128) {
                unsigned e = ss.sbuf[q];
                eval_pair(X, lab, (int)(e >> 13), (int)(e & 8191u));
            }
        } else {
            // overflow (rare; correctness guard): direct re-screen of this tile
#pragma unroll 1
            for (int j = 0; j < TJ; ++j) {
                float4 b0 = ss.sj[j][0];
                float4 b1 = ss.sj[j][1];
                float mhj = ss.smhj[j];
                int    jg = bj * TJ + j;
#pragma unroll 1
                for (int r = 0; r < 2; r++) {
                    float dot = fmaf(a[r][0].x, b0.x, mhj);
                    dot = fmaf(a[r][0].y, b0.y, dot);
                    dot = fmaf(a[r][0].z, b0.z, dot);
                    dot = fmaf(a[r][0].w, b0.w, dot);
                    dot = fmaf(a[r][1].x, b1.x, dot);
                    dot = fmaf(a[r][1].y, b1.y, dot);
                    dot = fmaf(a[r][1].z, b1.z, dot);
                    dot = fmaf(a[r][1].w, b1.w, dot);
                    if (dot > ci[r]) eval_pair(X, lab, ib[r], jg);
                }
            }
        }
    }

    // ---------------- completion ticket; last block finalizes ----------------
    __threadfence();
    __syncthreads();
    if (t == 0) {
        int v = atomicAdd(&g_done, 1);
        s_last = (v == NBLK - 1) ? 1 : 0;
    }
    __syncthreads();
    if (!s_last) return;

    // last block: reduce pos term + neg term, write loss, reset accumulators
    double part = 0.0;
#pragma unroll
    for (int q = 0; q < 4; q++) {
        int idx = q * 128 + t;
        double S1 = (double)g_s1[idx];
        double S2 = (double)g_s2[idx];
        part += (double)g_hist[idx >> 6] * S2 - S1 * S1;
    }
    // warp-level reduction, then across the 4 warps
#pragma unroll
    for (int s = 16; s > 0; s >>= 1)
        part += __shfl_down_sync(0xFFFFFFFFu, part, s);
    if ((t & 31) == 0) s_part[t >> 5] = part;
    __syncthreads();
    if (t == 0) {
        double pos  = 2.0 * (s_part[0] + s_part[1] + s_part[2] + s_part[3]);
        double loss = (pos + g_neg) / ((double)N_PTS * (double)(N_PTS - 1));
        out[0] = (float)loss;
    }
    // reset for the next graph replay
#pragma unroll
    for (int q = 0; q < 4; q++) {
        int idx = q * 128 + t;
        g_s1[idx] = 0.0f;
        g_s2[idx] = 0.0f;
    }
    if (t < NCLS) g_hist[t] = 0;
    if (t == 0) { g_neg = 0.0; g_done = 0; }
}

extern "C" void kernel_launch(void* const* d_in, const int* in_sizes, int n_in,
                              void* d_out, int out_size) {
    const float* X   = (const float*)d_in[0];
    const int*   lab = (const int*)d_in[1];
    float*       out = (float*)d_out;

    fused_kernel<<<NBLK, 128>>>(X, lab, out);
}